// round 15
// baseline (speedup 1.0000x reference)
#include <cuda_runtime.h>
#include <cuda_fp16.h>
#include <math.h>
#include <stdint.h>

// ---------------------------------------------------------------------------
// Problem constants
// ---------------------------------------------------------------------------
#define B_   64
#define C_   256
#define T_   32
#define H_   7
#define W_   7
#define HW_  49
#define N_   1568          // T*H*W
#define D_   512
#define KV_  97
#define KN_  300
#define NTOK 392
#define KTOT 2304          // C*9
#define MTOT 100352        // B*T*H*W
#define NBCE 98            // bce blocks (256 threads x 4 elems)

// Device scratch (static only)
__device__ __half g_xh[(size_t)B_ * N_ * C_];   // x transposed fp16: [b][n][c]
__device__ __half g_wh[(size_t)D_ * KTOT];      // weights fp16: [d][tap*256+c]
__device__ float g_wselv[B_ * C_];              // selected class weight rows
__device__ float g_wseln[B_ * C_];
__device__ float g_rowv[B_ * N_];               // CAM rows -> thresholded cams
__device__ float g_rown[B_ * N_];
__device__ float g_row0[MTOT];                  // logit partial, N-half 0
__device__ float g_row1[MTOT];                  // logit partial, N-half 1
__device__ float g_loss;                        // zero-init; reset each replay
__device__ unsigned g_cnt;                      // bce completion counter

// Spatial positions ordered interior-first (descending valid-tap count) so
// long CTAs launch in early waves and short ones fill the scheduling tail.
__constant__ int c_p_order[49] = {
    8, 9, 10, 11, 12, 15, 16, 17, 18, 19, 22, 23, 24, 25, 26,
    29, 30, 31, 32, 33, 36, 37, 38, 39, 40,                      // interior (9 taps)
    1, 2, 3, 4, 5, 43, 44, 45, 46, 47, 7, 14, 21, 28, 35,
    13, 20, 27, 34, 41,                                          // edges (6 taps)
    0, 6, 42, 48                                                 // corners (4 taps)
};

// ---------------------------------------------------------------------------
// PTX helpers (compute_103-safe: sm_80-era features only)
// ---------------------------------------------------------------------------
__device__ __forceinline__ uint32_t smem_u32(const void* p) {
    uint32_t a;
    asm("{ .reg .u64 t; cvta.to.shared.u64 t, %1; cvt.u32.u64 %0, t; }"
        : "=r"(a) : "l"(p));
    return a;
}
__device__ __forceinline__ void cp16(uint32_t dst, const void* src) {
    asm volatile("cp.async.cg.shared.global [%0], [%1], 16;"
                 :: "r"(dst), "l"(src) : "memory");
}
#define CP_COMMIT() asm volatile("cp.async.commit_group;" ::: "memory")
#define CP_WAIT0()  asm volatile("cp.async.wait_group 0;" ::: "memory")

__device__ __forceinline__ uint32_t swz128(uint32_t off) {
    return off ^ ((off >> 3) & 0x70);
}
__device__ __forceinline__ void ldsm4(uint32_t* r, uint32_t addr) {
    asm volatile("ldmatrix.sync.aligned.m8n8.x4.shared.b16 {%0,%1,%2,%3}, [%4];"
                 : "=r"(r[0]), "=r"(r[1]), "=r"(r[2]), "=r"(r[3]) : "r"(addr));
}
// fp16 x fp16 -> fp16 accumulate
__device__ __forceinline__ void mma_f16(uint32_t* c, const uint32_t* a,
                                        const uint32_t* b) {
    asm volatile("mma.sync.aligned.m16n8k16.row.col.f16.f16.f16.f16 "
                 "{%0,%1}, {%2,%3,%4,%5}, {%6,%7}, {%0,%1};"
                 : "+r"(c[0]), "+r"(c[1])
                 : "r"(a[0]), "r"(a[1]), "r"(a[2]), "r"(a[3]),
                   "r"(b[0]), "r"(b[1]));
}

// ---------------------------------------------------------------------------
// weights: g_wh[d][tap*256+c] = fp16(conv_w[d][c*9+tap])
// ---------------------------------------------------------------------------
__global__ void wh_kernel(const float* __restrict__ cw) {
    int o = blockIdx.x * 256 + threadIdx.x;
    if (o >= D_ * KTOT) return;
    int d = o / KTOT;
    int k = o - d * KTOT;
    int tap = k >> 8;
    int c = k & 255;
    g_wh[o] = __float2half(cw[d * KTOT + c * 9 + tap]);
}

// per-b argmax over both heads; copy selected weight rows
__global__ void __launch_bounds__(256) argmax_sel_kernel(
    const float* __restrict__ lv, const float* __restrict__ ln,
    const float* __restrict__ wpv, const float* __restrict__ wpn) {
    __shared__ float rv[256];
    __shared__ int   ri[256];
    int tid = threadIdx.x;
    int b = blockIdx.x;
    for (int head = 0; head < 2; head++) {
        const float* lg = head ? (ln + b * KN_) : (lv + b * KV_);
        int K = head ? KN_ : KV_;
        float best = -INFINITY; int bi = 0x7fffffff;
        for (int k = tid; k < K; k += 256) {
            float val = lg[k];
            if (val > best) { best = val; bi = k; }
        }
        rv[tid] = best; ri[tid] = bi;
        __syncthreads();
        for (int s = 128; s > 0; s >>= 1) {
            if (tid < s) {
                float ov = rv[tid + s]; int oi = ri[tid + s];
                if (ov > rv[tid] || (ov == rv[tid] && oi < ri[tid])) {
                    rv[tid] = ov; ri[tid] = oi;
                }
            }
            __syncthreads();
        }
        int top = ri[0];
        __syncthreads();
        if (head) g_wseln[b * C_ + tid] = wpn[top * C_ + tid];
        else      g_wselv[b * C_ + tid] = wpv[top * C_ + tid];
    }
}

// ---------------------------------------------------------------------------
// x transpose (fp16) + fused CAM dots, full C in one block (plain stores).
// grid (49, 64), block (32, 8).  [R9 v1 — known-good 42us]
// ---------------------------------------------------------------------------
__global__ void __launch_bounds__(256) xb_cam_kernel(const float* __restrict__ x) {
    __shared__ float tile[32][33];
    __shared__ float wsv[C_], wsn[C_];
    __shared__ float red[2][8][33];
    int b = blockIdx.y, n0 = blockIdx.x * 32;
    int tx = threadIdx.x, ty = threadIdx.y;
    int tid = ty * 32 + tx;
    const float* xp = x + (size_t)b * C_ * N_;

    wsv[tid] = g_wselv[b * C_ + tid];
    wsn[tid] = g_wseln[b * C_ + tid];

    float sv = 0.0f, sn = 0.0f;
    for (int c0 = 0; c0 < C_; c0 += 32) {
        __syncthreads();
#pragma unroll
        for (int i = 0; i < 4; i++)
            tile[ty + 8 * i][tx] = xp[(size_t)(c0 + ty + 8 * i) * N_ + n0 + tx];
        __syncthreads();
#pragma unroll
        for (int i = 0; i < 4; i++)
            g_xh[((size_t)b * N_ + n0 + ty + 8 * i) * C_ + c0 + tx] =
                __float2half(tile[tx][ty + 8 * i]);
#pragma unroll
        for (int i = 0; i < 4; i++) {
            float xv = tile[ty + 8 * i][tx];
            sv = fmaf(wsv[c0 + ty + 8 * i], xv, sv);
            sn = fmaf(wsn[c0 + ty + 8 * i], xv, sn);
        }
    }
    __syncthreads();
    red[0][ty][tx] = sv;
    red[1][ty][tx] = sn;
    __syncthreads();
    if (ty < 2) {
        float s = 0.0f;
#pragma unroll
        for (int k = 0; k < 8; k++) s += red[ty][k][tx];
        float* dst = ty ? g_rown : g_rowv;
        dst[b * N_ + n0 + tx] = s;
    }
}

// ---------------------------------------------------------------------------
// CAM select kernel: grid (64, 2), 512 threads. Min-max normalize + EXACT
// 392nd-largest via 3-level radix select on float bits; thresholds in place.
// ---------------------------------------------------------------------------
__global__ void __launch_bounds__(512) cam_select_kernel() {
    __shared__ float row[N_];
    __shared__ unsigned hist[2048];
    __shared__ unsigned scan[512];
    __shared__ float rA[512], rB[512];
    __shared__ unsigned s_sel[2];
    int tid = threadIdx.x;
    int b = blockIdx.x;
    float* src = blockIdx.y ? g_rown : g_rowv;

    for (int n = tid; n < N_; n += 512) row[n] = src[b * N_ + n];
    __syncthreads();

    float mn = INFINITY, mx = -INFINITY;
    for (int n = tid; n < N_; n += 512) {
        float v = row[n];
        mn = fminf(mn, v);
        mx = fmaxf(mx, v);
    }
    rA[tid] = mn; rB[tid] = mx;
    __syncthreads();
    for (int s = 256; s > 0; s >>= 1) {
        if (tid < s) {
            rA[tid] = fminf(rA[tid], rA[tid + s]);
            rB[tid] = fmaxf(rB[tid], rB[tid + s]);
        }
        __syncthreads();
    }
    mn = rA[0]; mx = rB[0];
    __syncthreads();
    float rng = mx - mn;
    for (int n = tid; n < N_; n += 512)
        row[n] = (row[n] - mn) / rng;
    __syncthreads();

    unsigned prefix = 0, pmask = 0, k = NTOK;
#pragma unroll
    for (int lvl = 0; lvl < 3; lvl++) {
        int shift = (lvl == 0) ? 21 : (lvl == 1) ? 10 : 0;
        unsigned nb = (lvl == 2) ? 1024u : 2048u;
        for (int i = tid; i < 2048; i += 512) hist[i] = 0;
        __syncthreads();
        for (int n = tid; n < N_; n += 512) {
            unsigned bits = __float_as_uint(row[n]);
            if ((bits & pmask) == prefix)
                atomicAdd(&hist[(bits >> shift) & (nb - 1u)], 1u);
        }
        __syncthreads();
        int G = nb / 512;
        unsigned gsum = 0;
        for (int i = 0; i < G; i++) gsum += hist[tid * G + i];
        scan[tid] = gsum;
        __syncthreads();
        for (int s = 1; s < 512; s <<= 1) {
            unsigned v = (tid + s < 512) ? scan[tid + s] : 0u;
            __syncthreads();
            scan[tid] += v;
            __syncthreads();
        }
        unsigned cum = (tid + 1 < 512) ? scan[tid + 1] : 0u;
        for (int i = G - 1; i >= 0; i--) {
            int bbin = tid * G + i;
            unsigned h = hist[bbin];
            cum += h;
            if (cum >= k && (cum - h) < k) {
                s_sel[0] = (unsigned)bbin;
                s_sel[1] = cum - h;
            }
        }
        __syncthreads();
        k -= s_sel[1];
        prefix |= s_sel[0] << shift;
        pmask |= (nb - 1u) << shift;
        __syncthreads();
    }
    float thr = __uint_as_float(prefix);
    for (int n = tid; n < N_; n += 512) {
        float v = row[n];
        src[b * N_ + n] = (v >= thr) ? v : 0.0f;
    }
}

// ---------------------------------------------------------------------------
// Implicit-GEMM conv via mma.sync fp16 (fp16 accum), spatially-grouped tiles.
// Valid-tap skipping (interior 36 K-chunks, edges 24, corners 16). CTA tile
// 128x256, 8 warps, warp tile 64x64, 2 CTAs/SM, one __syncthreads/chunk.
// Epilogue: bias+relu+score dot -> PLAIN store into g_row{0,1}[m] (unique slot
// per CTA/row, no atomics, no pre-zeroing needed).
// Grid: 49 p-values (interior first) x 16 bt-subtiles x 2 N-halves.
// ---------------------------------------------------------------------------
#define SA_(s)   ((uint32_t)(s) * 16384u)               // 2 x 16KB (A: 128x128B)
#define SB_(s)   (32768u + (uint32_t)(s) * 32768u)      // 2 x 32KB (B: 256x128B)
#define OFF_RED  98304u                                 // 128 floats
#define OFF_CB   98816u                                 // 256 floats
#define OFF_SW   99840u                                 // 256 floats
#define SMEM_DYN 100864u

__global__ void __launch_bounds__(256, 2) gemm_kernel(
    const float* __restrict__ conv_b,
    const float* __restrict__ score_w) {
    extern __shared__ char smem[];
    uint32_t sbase = smem_u32(smem);
    int tid = threadIdx.x, wid = tid >> 5, lane = tid & 31;

    int idx = blockIdx.x;
    int nt = idx & 1;            // N half
    int r  = idx >> 1;           // 0..783
    int pp = c_p_order[r >> 4];  // spatial position, interior-first
    int sub = r & 15;            // bt subtile: rows bt in [sub*128, sub*128+128)
    int hh = pp / 7, ww = pp - (pp / 7) * 7;
    int dbase = nt * 256;

    // valid taps for this position
    int taps[9], ntap = 0;
#pragma unroll
    for (int tap = 0; tap < 9; tap++) {
        int dh = tap / 3 - 1, dw = tap - (tap / 3) * 3 - 1;
        if ((unsigned)(hh + dh) < 7u && (unsigned)(ww + dw) < 7u)
            taps[ntap++] = tap;
    }
    int nchunks = ntap << 2;

    float* s_red = (float*)(smem + OFF_RED);
    float* s_cb  = (float*)(smem + OFF_CB);
    float* s_sw  = (float*)(smem + OFF_SW);
    if (tid < 128) s_red[tid] = 0.0f;
    s_cb[tid] = conv_b[dbase + tid];
    s_sw[tid] = score_w[dbase + tid];

    int rb = tid >> 3, seg = tid & 7;
    uint32_t bt49[4];
#pragma unroll
    for (int j = 0; j < 4; j++)
        bt49[j] = (uint32_t)(sub * 128 + rb + 32 * j) * 49u;

    auto load_chunk = [&](int kc, int stage) {
        int tap = taps[kc >> 2], c0 = (kc & 3) << 6;
        int dh = tap / 3 - 1, dw = tap - (tap / 3) * 3 - 1;
        int spat = (hh + dh) * 7 + (ww + dw);
        uint32_t sa = sbase + SA_(stage);
        uint32_t sbB = sbase + SB_(stage);
#pragma unroll
        for (int j = 0; j < 4; j++) {
            uint32_t eoff = (bt49[j] + (uint32_t)spat) * (uint32_t)C_
                            + (uint32_t)c0 + seg * 8u;
            uint32_t doff = (uint32_t)(rb + 32 * j) * 128u + seg * 16u;
            cp16(sa + swz128(doff), g_xh + eoff);
        }
        uint32_t koff = (uint32_t)(tap * 256 + c0) + seg * 8u;
#pragma unroll
        for (int j = 0; j < 8; j++) {
            uint32_t drow = (uint32_t)(rb + 32 * j);
            uint32_t eoff = (uint32_t)(dbase + drow) * (uint32_t)KTOT + koff;
            cp16(sbB + swz128(drow * 128u + seg * 16u), g_wh + eoff);
        }
    };

    uint32_t acc[4][8][2];
#pragma unroll
    for (int i = 0; i < 4; i++)
#pragma unroll
        for (int j = 0; j < 8; j++) { acc[i][j][0] = 0u; acc[i][j][1] = 0u; }

    int wm = wid >> 2, wn = wid & 3;     // 2(M) x 4(N) warps, tile 64x64
    int q = lane >> 3, g = lane & 7;
    int a_row = (q & 1) * 8 + g, a_k = (q >> 1) * 8;
    int b_row = (q >> 1) * 8 + g, b_k = (q & 1) * 8;

    load_chunk(0, 0);
    CP_COMMIT();

    for (int kc = 0; kc < nchunks; kc++) {
        int st = kc & 1;
        CP_WAIT0();
        __syncthreads();
        if (kc + 1 < nchunks) {
            load_chunk(kc + 1, st ^ 1);
            CP_COMMIT();
        }

        uint32_t sa = sbase + SA_(st);
        uint32_t sbB = sbase + SB_(st);
#pragma unroll
        for (int k0 = 0; k0 < 64; k0 += 16) {
            uint32_t af[4][4], bf[4][4];
#pragma unroll
            for (int i = 0; i < 4; i++)
                ldsm4(af[i], sa + swz128((uint32_t)(wm * 64 + i * 16 + a_row) * 128u
                                         + (uint32_t)(k0 + a_k) * 2u));
#pragma unroll
            for (int j2 = 0; j2 < 4; j2++)
                ldsm4(bf[j2], sbB + swz128((uint32_t)(wn * 64 + j2 * 16 + b_row) * 128u
                                           + (uint32_t)(k0 + b_k) * 2u));
#pragma unroll
            for (int i = 0; i < 4; i++)
#pragma unroll
                for (int j = 0; j < 8; j++) {
                    const uint32_t* bp = (j & 1) ? (bf[j >> 1] + 2) : bf[j >> 1];
                    mma_f16(acc[i][j], af[i], bp);
                }
        }
    }

    // Epilogue: bias + relu + score dot; per-row partial sums
    __syncthreads();
    int t4 = lane & 3, gg = lane >> 2;
#pragma unroll
    for (int i = 0; i < 4; i++) {
        int r0 = wm * 64 + i * 16 + gg;
        float s0 = 0.0f, s1 = 0.0f;
#pragma unroll
        for (int j = 0; j < 8; j++) {
            int dl = wn * 64 + j * 8 + 2 * t4;
            float cb0 = s_cb[dl], cb1 = s_cb[dl + 1];
            float sw0 = s_sw[dl], sw1 = s_sw[dl + 1];
            float2 p0 = __half22float2(*(const __half2*)&acc[i][j][0]);
            float2 p1 = __half22float2(*(const __half2*)&acc[i][j][1]);
            s0 = fmaf(fmaxf(p0.x + cb0, 0.0f), sw0, s0);
            s0 = fmaf(fmaxf(p0.y + cb1, 0.0f), sw1, s0);
            s1 = fmaf(fmaxf(p1.x + cb0, 0.0f), sw0, s1);
            s1 = fmaf(fmaxf(p1.y + cb1, 0.0f), sw1, s1);
        }
        s0 += __shfl_xor_sync(0xFFFFFFFFu, s0, 1);
        s0 += __shfl_xor_sync(0xFFFFFFFFu, s0, 2);
        s1 += __shfl_xor_sync(0xFFFFFFFFu, s1, 1);
        s1 += __shfl_xor_sync(0xFFFFFFFFu, s1, 2);
        if (t4 == 0) {
            atomicAdd(&s_red[r0], s0);
            atomicAdd(&s_red[r0 + 8], s1);
        }
    }
    __syncthreads();
    if (tid < 128) {
        // row -> original m: bt = sub*128 + tid; m = (bt/32)*1568 + (bt%32)*49 + p
        int m = (sub * 4 + (tid >> 5)) * N_ + (tid & 31) * HW_ + pp;
        (nt ? g_row1 : g_row0)[m] = s_red[tid];
    }
}

// ---------------------------------------------------------------------------
// BCE + fused finalize: 98 blocks x 256 threads x 4 elems; completion-counter
// last block writes the mean and resets g_cnt/g_loss for the next replay.
// ---------------------------------------------------------------------------
__global__ void __launch_bounds__(256) bce_fin_kernel(const float* __restrict__ sb,
                                                      float* __restrict__ out) {
    int tid = threadIdx.x;
    int m4 = blockIdx.x * 256 + tid;           // float4 index
    float sbias = sb[0];
    float4 l0 = ((const float4*)g_row0)[m4];
    float4 l1 = ((const float4*)g_row1)[m4];
    float4 yv = ((const float4*)g_rowv)[m4];
    float4 yn = ((const float4*)g_rown)[m4];
    float lg[4] = {l0.x + l1.x + sbias, l0.y + l1.y + sbias,
                   l0.z + l1.z + sbias, l0.w + l1.w + sbias};
    float yy[4] = {fmaxf(yv.x, yn.x), fmaxf(yv.y, yn.y),
                   fmaxf(yv.z, yn.z), fmaxf(yv.w, yn.w)};
    float v = 0.0f;
#pragma unroll
    for (int i = 0; i < 4; i++) {
        float ax = fabsf(lg[i]);
        float sp = fmaxf(lg[i], 0.0f) + log1pf(expf(-ax));
        v += sp - yy[i] * lg[i];
    }
#pragma unroll
    for (int s = 16; s > 0; s >>= 1)
        v += __shfl_down_sync(0xFFFFFFFFu, v, s);
    __shared__ float red[8];
    if ((tid & 31) == 0) red[tid >> 5] = v;
    __syncthreads();
    if (tid < 8) {
        float r = red[tid];
#pragma unroll
        for (int s = 4; s > 0; s >>= 1)
            r += __shfl_down_sync(0xFFu, r, s);
        if (tid == 0) {
            atomicAdd(&g_loss, r);
            __threadfence();
            unsigned done = atomicAdd(&g_cnt, 1u);
            if (done == NBCE - 1) {
                float total = atomicAdd(&g_loss, 0.0f);  // ordered read
                out[0] = total * (1.0f / (float)MTOT);
                g_loss = 0.0f;                           // reset for next replay
                g_cnt = 0;
            }
        }
    }
}

// ---------------------------------------------------------------------------
// launch (single stream — overlap attempts were neutral/harmful; R9 order)
// ---------------------------------------------------------------------------
extern "C" void kernel_launch(void* const* d_in, const int* in_sizes, int n_in,
                              void* d_out, int out_size) {
    const float* x   = (const float*)d_in[0];
    const float* lv  = (const float*)d_in[1];
    const float* ln  = (const float*)d_in[2];
    const float* wpv = (const float*)d_in[3];
    const float* wpn = (const float*)d_in[4];
    const float* cw  = (const float*)d_in[5];
    const float* cb  = (const float*)d_in[6];
    const float* sw  = (const float*)d_in[7];
    const float* sbv = (const float*)d_in[8];
    float* out = (float*)d_out;

    cudaFuncSetAttribute(gemm_kernel,
                         cudaFuncAttributeMaxDynamicSharedMemorySize, SMEM_DYN);

    wh_kernel<<<(D_ * KTOT + 255) / 256, 256>>>(cw);
    argmax_sel_kernel<<<B_, 256>>>(lv, ln, wpv, wpn);
    {
        dim3 g(49, 64), b(32, 8);
        xb_cam_kernel<<<g, b>>>(x);
    }
    {
        dim3 g(B_, 2);
        cam_select_kernel<<<g, 512>>>();
    }
    gemm_kernel<<<49 * 16 * 2, 256, SMEM_DYN>>>(cb, sw);
    bce_fin_kernel<<<NBCE, 256>>>(sbv, out);
}

// round 16
// speedup vs baseline: 1.0013x; 1.0013x over previous
#include <cuda_runtime.h>
#include <cuda_fp16.h>
#include <math.h>
#include <stdint.h>

// ---------------------------------------------------------------------------
// Problem constants
// ---------------------------------------------------------------------------
#define B_   64
#define C_   256
#define T_   32
#define H_   7
#define W_   7
#define HW_  49
#define N_   1568          // T*H*W
#define D_   512
#define KV_  97
#define KN_  300
#define NTOK 392
#define KTOT 2304          // C*9
#define MTOT 100352        // B*T*H*W
#define NBCE 98            // bce blocks (256 threads x 4 elems)

// Device scratch (static only)
__device__ __half g_xh[(size_t)B_ * N_ * C_];   // x transposed fp16: [b][n][c]
__device__ __half g_wh[(size_t)D_ * KTOT];      // weights fp16: [d][tap*256+c]
__device__ float g_wselv[B_ * C_];              // selected class weight rows
__device__ float g_wseln[B_ * C_];
__device__ float g_rowv[B_ * N_];               // CAM rows -> thresholded cams
__device__ float g_rown[B_ * N_];
__device__ float g_row0[MTOT];                  // logit partial, N-half 0
__device__ float g_row1[MTOT];                  // logit partial, N-half 1
__device__ float g_loss;                        // zero-init; reset each replay
__device__ unsigned g_cnt;                      // bce completion counter

// Spatial positions ordered interior-first (descending valid-tap count) so
// long CTAs launch in early waves and short ones fill the scheduling tail.
__constant__ int c_p_order[49] = {
    8, 9, 10, 11, 12, 15, 16, 17, 18, 19, 22, 23, 24, 25, 26,
    29, 30, 31, 32, 33, 36, 37, 38, 39, 40,                      // interior (9 taps)
    1, 2, 3, 4, 5, 43, 44, 45, 46, 47, 7, 14, 21, 28, 35,
    13, 20, 27, 34, 41,                                          // edges (6 taps)
    0, 6, 42, 48                                                 // corners (4 taps)
};

// ---------------------------------------------------------------------------
// PTX helpers (compute_103-safe: sm_80-era features only)
// ---------------------------------------------------------------------------
__device__ __forceinline__ uint32_t smem_u32(const void* p) {
    uint32_t a;
    asm("{ .reg .u64 t; cvta.to.shared.u64 t, %1; cvt.u32.u64 %0, t; }"
        : "=r"(a) : "l"(p));
    return a;
}
__device__ __forceinline__ void cp16(uint32_t dst, const void* src) {
    asm volatile("cp.async.cg.shared.global [%0], [%1], 16;"
                 :: "r"(dst), "l"(src) : "memory");
}
#define CP_COMMIT() asm volatile("cp.async.commit_group;" ::: "memory")
#define CP_WAIT0()  asm volatile("cp.async.wait_group 0;" ::: "memory")

__device__ __forceinline__ uint32_t swz128(uint32_t off) {
    return off ^ ((off >> 3) & 0x70);
}
__device__ __forceinline__ void ldsm4(uint32_t* r, uint32_t addr) {
    asm volatile("ldmatrix.sync.aligned.m8n8.x4.shared.b16 {%0,%1,%2,%3}, [%4];"
                 : "=r"(r[0]), "=r"(r[1]), "=r"(r[2]), "=r"(r[3]) : "r"(addr));
}
// fp16 x fp16 -> fp16 accumulate
__device__ __forceinline__ void mma_f16(uint32_t* c, const uint32_t* a,
                                        const uint32_t* b) {
    asm volatile("mma.sync.aligned.m16n8k16.row.col.f16.f16.f16.f16 "
                 "{%0,%1}, {%2,%3,%4,%5}, {%6,%7}, {%0,%1};"
                 : "+r"(c[0]), "+r"(c[1])
                 : "r"(a[0]), "r"(a[1]), "r"(a[2]), "r"(a[3]),
                   "r"(b[0]), "r"(b[1]));
}

// ---------------------------------------------------------------------------
// weights: g_wh[d][tap*256+c] = fp16(conv_w[d][c*9+tap])
// ---------------------------------------------------------------------------
__global__ void wh_kernel(const float* __restrict__ cw) {
    int o = blockIdx.x * 256 + threadIdx.x;
    if (o >= D_ * KTOT) return;
    int d = o / KTOT;
    int k = o - d * KTOT;
    int tap = k >> 8;
    int c = k & 255;
    g_wh[o] = __float2half(cw[d * KTOT + c * 9 + tap]);
}

// per-b argmax over both heads; copy selected weight rows
__global__ void __launch_bounds__(256) argmax_sel_kernel(
    const float* __restrict__ lv, const float* __restrict__ ln,
    const float* __restrict__ wpv, const float* __restrict__ wpn) {
    __shared__ float rv[256];
    __shared__ int   ri[256];
    int tid = threadIdx.x;
    int b = blockIdx.x;
    for (int head = 0; head < 2; head++) {
        const float* lg = head ? (ln + b * KN_) : (lv + b * KV_);
        int K = head ? KN_ : KV_;
        float best = -INFINITY; int bi = 0x7fffffff;
        for (int k = tid; k < K; k += 256) {
            float val = lg[k];
            if (val > best) { best = val; bi = k; }
        }
        rv[tid] = best; ri[tid] = bi;
        __syncthreads();
        for (int s = 128; s > 0; s >>= 1) {
            if (tid < s) {
                float ov = rv[tid + s]; int oi = ri[tid + s];
                if (ov > rv[tid] || (ov == rv[tid] && oi < ri[tid])) {
                    rv[tid] = ov; ri[tid] = oi;
                }
            }
            __syncthreads();
        }
        int top = ri[0];
        __syncthreads();
        if (head) g_wseln[b * C_ + tid] = wpn[top * C_ + tid];
        else      g_wselv[b * C_ + tid] = wpv[top * C_ + tid];
    }
}

// ---------------------------------------------------------------------------
// x transpose (fp16) + fused CAM dots, full C in one block (plain stores).
// grid (49, 64), block (32, 8).  [R9 v1 — known-good 42us]
// ---------------------------------------------------------------------------
__global__ void __launch_bounds__(256) xb_cam_kernel(const float* __restrict__ x) {
    __shared__ float tile[32][33];
    __shared__ float wsv[C_], wsn[C_];
    __shared__ float red[2][8][33];
    int b = blockIdx.y, n0 = blockIdx.x * 32;
    int tx = threadIdx.x, ty = threadIdx.y;
    int tid = ty * 32 + tx;
    const float* xp = x + (size_t)b * C_ * N_;

    wsv[tid] = g_wselv[b * C_ + tid];
    wsn[tid] = g_wseln[b * C_ + tid];

    float sv = 0.0f, sn = 0.0f;
    for (int c0 = 0; c0 < C_; c0 += 32) {
        __syncthreads();
#pragma unroll
        for (int i = 0; i < 4; i++)
            tile[ty + 8 * i][tx] = xp[(size_t)(c0 + ty + 8 * i) * N_ + n0 + tx];
        __syncthreads();
#pragma unroll
        for (int i = 0; i < 4; i++)
            g_xh[((size_t)b * N_ + n0 + ty + 8 * i) * C_ + c0 + tx] =
                __float2half(tile[tx][ty + 8 * i]);
#pragma unroll
        for (int i = 0; i < 4; i++) {
            float xv = tile[ty + 8 * i][tx];
            sv = fmaf(wsv[c0 + ty + 8 * i], xv, sv);
            sn = fmaf(wsn[c0 + ty + 8 * i], xv, sn);
        }
    }
    __syncthreads();
    red[0][ty][tx] = sv;
    red[1][ty][tx] = sn;
    __syncthreads();
    if (ty < 2) {
        float s = 0.0f;
#pragma unroll
        for (int k = 0; k < 8; k++) s += red[ty][k][tx];
        float* dst = ty ? g_rown : g_rowv;
        dst[b * N_ + n0 + tx] = s;
    }
}

// ---------------------------------------------------------------------------
// CAM select kernel: grid (64, 2), 512 threads. Min-max normalize + EXACT
// 392nd-largest via 3-level radix select on float bits; thresholds in place.
// ---------------------------------------------------------------------------
__global__ void __launch_bounds__(512) cam_select_kernel() {
    __shared__ float row[N_];
    __shared__ unsigned hist[2048];
    __shared__ unsigned scan[512];
    __shared__ float rA[512], rB[512];
    __shared__ unsigned s_sel[2];
    int tid = threadIdx.x;
    int b = blockIdx.x;
    float* src = blockIdx.y ? g_rown : g_rowv;

    for (int n = tid; n < N_; n += 512) row[n] = src[b * N_ + n];
    __syncthreads();

    float mn = INFINITY, mx = -INFINITY;
    for (int n = tid; n < N_; n += 512) {
        float v = row[n];
        mn = fminf(mn, v);
        mx = fmaxf(mx, v);
    }
    rA[tid] = mn; rB[tid] = mx;
    __syncthreads();
    for (int s = 256; s > 0; s >>= 1) {
        if (tid < s) {
            rA[tid] = fminf(rA[tid], rA[tid + s]);
            rB[tid] = fmaxf(rB[tid], rB[tid + s]);
        }
        __syncthreads();
    }
    mn = rA[0]; mx = rB[0];
    __syncthreads();
    float rng = mx - mn;
    for (int n = tid; n < N_; n += 512)
        row[n] = (row[n] - mn) / rng;
    __syncthreads();

    unsigned prefix = 0, pmask = 0, k = NTOK;
#pragma unroll
    for (int lvl = 0; lvl < 3; lvl++) {
        int shift = (lvl == 0) ? 21 : (lvl == 1) ? 10 : 0;
        unsigned nb = (lvl == 2) ? 1024u : 2048u;
        for (int i = tid; i < 2048; i += 512) hist[i] = 0;
        __syncthreads();
        for (int n = tid; n < N_; n += 512) {
            unsigned bits = __float_as_uint(row[n]);
            if ((bits & pmask) == prefix)
                atomicAdd(&hist[(bits >> shift) & (nb - 1u)], 1u);
        }
        __syncthreads();
        int G = nb / 512;
        unsigned gsum = 0;
        for (int i = 0; i < G; i++) gsum += hist[tid * G + i];
        scan[tid] = gsum;
        __syncthreads();
        for (int s = 1; s < 512; s <<= 1) {
            unsigned v = (tid + s < 512) ? scan[tid + s] : 0u;
            __syncthreads();
            scan[tid] += v;
            __syncthreads();
        }
        unsigned cum = (tid + 1 < 512) ? scan[tid + 1] : 0u;
        for (int i = G - 1; i >= 0; i--) {
            int bbin = tid * G + i;
            unsigned h = hist[bbin];
            cum += h;
            if (cum >= k && (cum - h) < k) {
                s_sel[0] = (unsigned)bbin;
                s_sel[1] = cum - h;
            }
        }
        __syncthreads();
        k -= s_sel[1];
        prefix |= s_sel[0] << shift;
        pmask |= (nb - 1u) << shift;
        __syncthreads();
    }
    float thr = __uint_as_float(prefix);
    for (int n = tid; n < N_; n += 512) {
        float v = row[n];
        src[b * N_ + n] = (v >= thr) ? v : 0.0f;
    }
}

// ---------------------------------------------------------------------------
// Implicit-GEMM conv via mma.sync fp16 (fp16 accum), spatially-grouped tiles.
// Valid-tap skipping (interior 36 K-chunks, edges 24, corners 16). CTA tile
// 128x256, 8 warps, warp tile 64x64, 2 CTAs/SM, one __syncthreads/chunk.
// Epilogue: bias+relu+score dot -> PLAIN store into g_row{0,1}[m] (unique slot
// per CTA/row, no atomics, no pre-zeroing needed).
// Grid: 49 p-values (interior first) x 16 bt-subtiles x 2 N-halves.
// ---------------------------------------------------------------------------
#define SA_(s)   ((uint32_t)(s) * 16384u)               // 2 x 16KB (A: 128x128B)
#define SB_(s)   (32768u + (uint32_t)(s) * 32768u)      // 2 x 32KB (B: 256x128B)
#define OFF_RED  98304u                                 // 128 floats
#define OFF_CB   98816u                                 // 256 floats
#define OFF_SW   99840u                                 // 256 floats
#define SMEM_DYN 100864u

__global__ void __launch_bounds__(256, 2) gemm_kernel(
    const float* __restrict__ conv_b,
    const float* __restrict__ score_w) {
    extern __shared__ char smem[];
    uint32_t sbase = smem_u32(smem);
    int tid = threadIdx.x, wid = tid >> 5, lane = tid & 31;

    int idx = blockIdx.x;
    int nt = idx & 1;            // N half
    int r  = idx >> 1;           // 0..783
    int pp = c_p_order[r >> 4];  // spatial position, interior-first
    int sub = r & 15;            // bt subtile: rows bt in [sub*128, sub*128+128)
    int hh = pp / 7, ww = pp - (pp / 7) * 7;
    int dbase = nt * 256;

    // valid taps for this position
    int taps[9], ntap = 0;
#pragma unroll
    for (int tap = 0; tap < 9; tap++) {
        int dh = tap / 3 - 1, dw = tap - (tap / 3) * 3 - 1;
        if ((unsigned)(hh + dh) < 7u && (unsigned)(ww + dw) < 7u)
            taps[ntap++] = tap;
    }
    int nchunks = ntap << 2;

    float* s_red = (float*)(smem + OFF_RED);
    float* s_cb  = (float*)(smem + OFF_CB);
    float* s_sw  = (float*)(smem + OFF_SW);
    if (tid < 128) s_red[tid] = 0.0f;
    s_cb[tid] = conv_b[dbase + tid];
    s_sw[tid] = score_w[dbase + tid];

    int rb = tid >> 3, seg = tid & 7;
    uint32_t bt49[4];
#pragma unroll
    for (int j = 0; j < 4; j++)
        bt49[j] = (uint32_t)(sub * 128 + rb + 32 * j) * 49u;

    auto load_chunk = [&](int kc, int stage) {
        int tap = taps[kc >> 2], c0 = (kc & 3) << 6;
        int dh = tap / 3 - 1, dw = tap - (tap / 3) * 3 - 1;
        int spat = (hh + dh) * 7 + (ww + dw);
        uint32_t sa = sbase + SA_(stage);
        uint32_t sbB = sbase + SB_(stage);
#pragma unroll
        for (int j = 0; j < 4; j++) {
            uint32_t eoff = (bt49[j] + (uint32_t)spat) * (uint32_t)C_
                            + (uint32_t)c0 + seg * 8u;
            uint32_t doff = (uint32_t)(rb + 32 * j) * 128u + seg * 16u;
            cp16(sa + swz128(doff), g_xh + eoff);
        }
        uint32_t koff = (uint32_t)(tap * 256 + c0) + seg * 8u;
#pragma unroll
        for (int j = 0; j < 8; j++) {
            uint32_t drow = (uint32_t)(rb + 32 * j);
            uint32_t eoff = (uint32_t)(dbase + drow) * (uint32_t)KTOT + koff;
            cp16(sbB + swz128(drow * 128u + seg * 16u), g_wh + eoff);
        }
    };

    uint32_t acc[4][8][2];
#pragma unroll
    for (int i = 0; i < 4; i++)
#pragma unroll
        for (int j = 0; j < 8; j++) { acc[i][j][0] = 0u; acc[i][j][1] = 0u; }

    int wm = wid >> 2, wn = wid & 3;     // 2(M) x 4(N) warps, tile 64x64
    int q = lane >> 3, g = lane & 7;
    int a_row = (q & 1) * 8 + g, a_k = (q >> 1) * 8;
    int b_row = (q >> 1) * 8 + g, b_k = (q & 1) * 8;

    load_chunk(0, 0);
    CP_COMMIT();

    for (int kc = 0; kc < nchunks; kc++) {
        int st = kc & 1;
        CP_WAIT0();
        __syncthreads();
        if (kc + 1 < nchunks) {
            load_chunk(kc + 1, st ^ 1);
            CP_COMMIT();
        }

        uint32_t sa = sbase + SA_(st);
        uint32_t sbB = sbase + SB_(st);
#pragma unroll
        for (int k0 = 0; k0 < 64; k0 += 16) {
            uint32_t af[4][4], bf[4][4];
#pragma unroll
            for (int i = 0; i < 4; i++)
                ldsm4(af[i], sa + swz128((uint32_t)(wm * 64 + i * 16 + a_row) * 128u
                                         + (uint32_t)(k0 + a_k) * 2u));
#pragma unroll
            for (int j2 = 0; j2 < 4; j2++)
                ldsm4(bf[j2], sbB + swz128((uint32_t)(wn * 64 + j2 * 16 + b_row) * 128u
                                           + (uint32_t)(k0 + b_k) * 2u));
#pragma unroll
            for (int i = 0; i < 4; i++)
#pragma unroll
                for (int j = 0; j < 8; j++) {
                    const uint32_t* bp = (j & 1) ? (bf[j >> 1] + 2) : bf[j >> 1];
                    mma_f16(acc[i][j], af[i], bp);
                }
        }
    }

    // Epilogue: bias + relu + score dot; per-row partial sums
    __syncthreads();
    int t4 = lane & 3, gg = lane >> 2;
#pragma unroll
    for (int i = 0; i < 4; i++) {
        int r0 = wm * 64 + i * 16 + gg;
        float s0 = 0.0f, s1 = 0.0f;
#pragma unroll
        for (int j = 0; j < 8; j++) {
            int dl = wn * 64 + j * 8 + 2 * t4;
            float cb0 = s_cb[dl], cb1 = s_cb[dl + 1];
            float sw0 = s_sw[dl], sw1 = s_sw[dl + 1];
            float2 p0 = __half22float2(*(const __half2*)&acc[i][j][0]);
            float2 p1 = __half22float2(*(const __half2*)&acc[i][j][1]);
            s0 = fmaf(fmaxf(p0.x + cb0, 0.0f), sw0, s0);
            s0 = fmaf(fmaxf(p0.y + cb1, 0.0f), sw1, s0);
            s1 = fmaf(fmaxf(p1.x + cb0, 0.0f), sw0, s1);
            s1 = fmaf(fmaxf(p1.y + cb1, 0.0f), sw1, s1);
        }
        s0 += __shfl_xor_sync(0xFFFFFFFFu, s0, 1);
        s0 += __shfl_xor_sync(0xFFFFFFFFu, s0, 2);
        s1 += __shfl_xor_sync(0xFFFFFFFFu, s1, 1);
        s1 += __shfl_xor_sync(0xFFFFFFFFu, s1, 2);
        if (t4 == 0) {
            atomicAdd(&s_red[r0], s0);
            atomicAdd(&s_red[r0 + 8], s1);
        }
    }
    __syncthreads();
    if (tid < 128) {
        // row -> original m: bt = sub*128 + tid; m = (bt/32)*1568 + (bt%32)*49 + p
        int m = (sub * 4 + (tid >> 5)) * N_ + (tid & 31) * HW_ + pp;
        (nt ? g_row1 : g_row0)[m] = s_red[tid];
    }
}

// ---------------------------------------------------------------------------
// BCE + fused finalize: 98 blocks x 256 threads x 4 elems; completion-counter
// last block writes the mean and resets g_cnt/g_loss for the next replay.
// ---------------------------------------------------------------------------
__global__ void __launch_bounds__(256) bce_fin_kernel(const float* __restrict__ sb,
                                                      float* __restrict__ out) {
    int tid = threadIdx.x;
    int m4 = blockIdx.x * 256 + tid;           // float4 index
    float sbias = sb[0];
    float4 l0 = ((const float4*)g_row0)[m4];
    float4 l1 = ((const float4*)g_row1)[m4];
    float4 yv = ((const float4*)g_rowv)[m4];
    float4 yn = ((const float4*)g_rown)[m4];
    float lg[4] = {l0.x + l1.x + sbias, l0.y + l1.y + sbias,
                   l0.z + l1.z + sbias, l0.w + l1.w + sbias};
    float yy[4] = {fmaxf(yv.x, yn.x), fmaxf(yv.y, yn.y),
                   fmaxf(yv.z, yn.z), fmaxf(yv.w, yn.w)};
    float v = 0.0f;
#pragma unroll
    for (int i = 0; i < 4; i++) {
        float ax = fabsf(lg[i]);
        float sp = fmaxf(lg[i], 0.0f) + log1pf(expf(-ax));
        v += sp - yy[i] * lg[i];
    }
#pragma unroll
    for (int s = 16; s > 0; s >>= 1)
        v += __shfl_down_sync(0xFFFFFFFFu, v, s);
    __shared__ float red[8];
    if ((tid & 31) == 0) red[tid >> 5] = v;
    __syncthreads();
    if (tid < 8) {
        float r = red[tid];
#pragma unroll
        for (int s = 4; s > 0; s >>= 1)
            r += __shfl_down_sync(0xFFu, r, s);
        if (tid == 0) {
            atomicAdd(&g_loss, r);
            __threadfence();
            unsigned done = atomicAdd(&g_cnt, 1u);
            if (done == NBCE - 1) {
                float total = atomicAdd(&g_loss, 0.0f);  // ordered read
                out[0] = total * (1.0f / (float)MTOT);
                g_loss = 0.0f;                           // reset for next replay
                g_cnt = 0;
            }
        }
    }
}

// ---------------------------------------------------------------------------
// launch (single stream — overlap attempts were neutral/harmful; R9 order)
// ---------------------------------------------------------------------------
extern "C" void kernel_launch(void* const* d_in, const int* in_sizes, int n_in,
                              void* d_out, int out_size) {
    const float* x   = (const float*)d_in[0];
    const float* lv  = (const float*)d_in[1];
    const float* ln  = (const float*)d_in[2];
    const float* wpv = (const float*)d_in[3];
    const float* wpn = (const float*)d_in[4];
    const float* cw  = (const float*)d_in[5];
    const float* cb  = (const float*)d_in[6];
    const float* sw  = (const float*)d_in[7];
    const float* sbv = (const float*)d_in[8];
    float* out = (float*)d_out;

    cudaFuncSetAttribute(gemm_kernel,
                         cudaFuncAttributeMaxDynamicSharedMemorySize, SMEM_DYN);

    wh_kernel<<<(D_ * KTOT + 255) / 256, 256>>>(cw);
    argmax_sel_kernel<<<B_, 256>>>(lv, ln, wpv, wpn);
    {
        dim3 g(49, 64), b(32, 8);
        xb_cam_kernel<<<g, b>>>(x);
    }
    {
        dim3 g(B_, 2);
        cam_select_kernel<<<g, 512>>>();
    }
    gemm_kernel<<<49 * 16 * 2, 256, SMEM_DYN>>>(cb, sw);
    bce_fin_kernel<<<NBCE, 256>>>(sbv, out);
}